// round 5
// baseline (speedup 1.0000x reference)
#include <cuda_runtime.h>

// Problem constants (static in the reference: SIZES[g] = 256 + 16*g, B=16)
#define NB 16
#define IN_DIM 16
#define HID 64
#define OUTD 32
#define N_TOT 6016
#define N_PAIRS 2349056

// t scratch: per-node MLP output [N_TOT, 32] = 770 KB
__device__ float g_t[N_TOT * OUTD];
// per-graph sync counters (zero-init at load; reset by exit protocol each launch)
__device__ int g_done[NB];
__device__ int g_exit[NB];

// starts[g] = sum_{h<g} sizes[h]; starts[16] = 6016 (sentinel)
__constant__ int c_starts[NB + 1] = {
    0, 256, 528, 816, 1120, 1440, 1776, 2128,
    2496, 2880, 3280, 3696, 4128, 4576, 5040, 5520, 6016};
__constant__ int c_sizes[NB] = {
    256, 272, 288, 304, 320, 336, 352, 368,
    384, 400, 416, 432, 448, 464, 480, 496};
// pair_cum[g] = sum_{h<g} sizes[h]^2
__constant__ int c_paircum[NB] = {
    0, 65536, 139520, 222464, 314880, 417280, 530176, 654080,
    789504, 936960, 1096960, 1270016, 1456640, 1657344, 1872640, 2103040};

// ---------------------------------------------------------------------------
// Fused kernel: one block per global node row (b, i).
// Phase A: this block computes t[row] = relu(ape[row]@W1+b1)@W2+b2, publishes.
// Sync:    wait until all nb blocks of graph b have published their t row.
// Phase B: stream pair rows out[(paircum[b]+i*nb+j)] = t[row] + t[gbase+j].
// Counters self-reset via exit protocol so the kernel is replay-safe.
// ---------------------------------------------------------------------------
__global__ __launch_bounds__(256) void fused_kernel(
    const float* __restrict__ ape, const float* __restrict__ W1,
    const float* __restrict__ b1, const float* __restrict__ W2,
    const float* __restrict__ b2, float* __restrict__ out)
{
    const int row = blockIdx.x;

    // which graph does this row belong to (16-entry unrolled scan, constant mem)
    int b = 0;
#pragma unroll
    for (int g = 1; g < NB; g++) b += (row >= c_starts[g]) ? 1 : 0;

    const int gbase = c_starts[b];
    const int nb    = c_sizes[b];
    const int i     = row - gbase;
    const int orow0 = c_paircum[b] + i * nb;   // first output row for this (b,i)

    __shared__ float hid[HID];
    __shared__ __align__(16) float trow[OUTD];

    const int tid = threadIdx.x;

    // ---- Phase A: MLP for node 'row' ----
    if (tid < HID) {
        float v = __ldg(b1 + tid);
        const float* aprow = ape + (size_t)row * IN_DIM;
#pragma unroll
        for (int k = 0; k < IN_DIM; k++)
            v = fmaf(__ldg(aprow + k), __ldg(W1 + k * HID + tid), v);
        hid[tid] = fmaxf(v, 0.0f);
    }
    __syncthreads();
    if (tid < OUTD) {
        float v = __ldg(b2 + tid);
#pragma unroll
        for (int h = 0; h < HID; h++)
            v = fmaf(hid[h], __ldg(W2 + h * OUTD + tid), v);
        trow[tid] = v;
        g_t[(size_t)row * OUTD + tid] = v;   // publish our row
    }
    __syncthreads();

    // ---- Sync: publish count, wait for whole graph, exit-reset protocol ----
    if (tid == 0) {
        __threadfence();                      // t row visible before count
        atomicAdd(&g_done[b], 1);
        volatile int* dp = &g_done[b];
        while (*dp < nb) __nanosleep(128);
        __threadfence();                      // acquire: order t reads after flag
        // all peers provably past their wait once exit hits nb -> safe to reset
        if (atomicAdd(&g_exit[b], 1) == nb - 1) {
            atomicExch(&g_done[b], 0);
            atomicExch(&g_exit[b], 0);
        }
    }
    __syncthreads();

    // ---- Phase B: pair loop (roofline store stream, unchanged layout) ----
    const int q  = tid & 7;    // quad index (q*4 .. q*4+3 of the 32 outs)
    const int jl = tid >> 3;   // j lane (0..31)

    const float4 ti = *reinterpret_cast<const float4*>(trow + q * 4);
    const float4* __restrict__ gt4 = reinterpret_cast<const float4*>(g_t);
    float4* __restrict__ out4 = reinterpret_cast<float4*>(out);

    int j = jl;                // jl < 32 <= nb always -> at least one trip
    float4 tj = gt4[(size_t)(gbase + j) * 8 + q];   // plain load: g_t written this launch

    for (;;) {
        const int jn = j + 32;
        const bool more = jn < nb;
        float4 tn;
        if (more) tn = gt4[(size_t)(gbase + jn) * 8 + q];
        float4 r;
        r.x = ti.x + tj.x; r.y = ti.y + tj.y;
        r.z = ti.z + tj.z; r.w = ti.w + tj.w;
        __stcs(&out4[(size_t)(orow0 + j) * 8 + q], r);
        if (!more) break;
        j = jn; tj = tn;
    }
}

extern "C" void kernel_launch(void* const* d_in, const int* in_sizes, int n_in,
                              void* d_out, int out_size)
{
    const float* ape = (const float*)d_in[0];
    const float* W1  = (const float*)d_in[1];
    const float* b1  = (const float*)d_in[2];
    const float* W2  = (const float*)d_in[3];
    const float* b2  = (const float*)d_in[4];
    float* out = (float*)d_out;

    fused_kernel<<<N_TOT, 256>>>(ape, W1, b1, W2, b2, out);
}

// round 7
// speedup vs baseline: 1.3441x; 1.3441x over previous
#include <cuda_runtime.h>

// Problem constants (static in the reference: SIZES[g] = 256 + 16*g, B=16)
#define NB 16
#define IN_DIM 16
#define HID 64
#define OUTD 32
#define N_TOT 6016
#define N_PAIRS 2349056

#define GRIDB 592          // 148 SMs x 4 CTAs — provably co-resident (see launch_bounds)

// t scratch: per-node MLP output [N_TOT, 32] = 770 KB
__device__ float g_t[N_TOT * OUTD];
// grid barrier counters (zero at module load; reset by exit protocol each launch)
__device__ int g_done;
__device__ int g_exit;

// starts[g] = sum_{h<g} sizes[h]; starts[16] = 6016 (sentinel)
__constant__ int c_starts[NB + 1] = {
    0, 256, 528, 816, 1120, 1440, 1776, 2128,
    2496, 2880, 3280, 3696, 4128, 4576, 5040, 5520, 6016};
__constant__ int c_sizes[NB] = {
    256, 272, 288, 304, 320, 336, 352, 368,
    384, 400, 416, 432, 448, 464, 480, 496};
// pair_cum[g] = sum_{h<g} sizes[h]^2
__constant__ int c_paircum[NB] = {
    0, 65536, 139520, 222464, 314880, 417280, 530176, 654080,
    789504, 936960, 1096960, 1270016, 1456640, 1657344, 1872640, 2103040};

// ---------------------------------------------------------------------------
// Persistent fused kernel, 592 blocks x 256 threads (all co-resident).
// Phase A: 8 threads per node compute its MLP row (shuffle-shared hidden).
// Grid barrier (single, all-resident -> deadlock-free, self-resetting).
// Phase B: pair-row store stream, rows strided across blocks for balance.
// ---------------------------------------------------------------------------
__global__ __launch_bounds__(256, 4) void fused_kernel(
    const float* __restrict__ ape, const float* __restrict__ W1,
    const float* __restrict__ b1, const float* __restrict__ W2,
    const float* __restrict__ b2, float* __restrict__ out)
{
    const int tid  = threadIdx.x;
    const int gtid = blockIdx.x * 256 + tid;

    // ---- Phase A: MLP. 8 threads per node; lane p owns hidden h = p*8..p*8+7
    {
        const int node   = gtid >> 3;
        const int part   = gtid & 7;
        const bool active = node < N_TOT;
        const int nclamp = active ? node : 0;

        float a[IN_DIM];
        const float4* ap = reinterpret_cast<const float4*>(ape + (size_t)nclamp * IN_DIM);
#pragma unroll
        for (int k4 = 0; k4 < IN_DIM / 4; k4++) {
            float4 v = __ldg(ap + k4);
            a[k4 * 4 + 0] = v.x; a[k4 * 4 + 1] = v.y;
            a[k4 * 4 + 2] = v.z; a[k4 * 4 + 3] = v.w;
        }

        float hval[8];
#pragma unroll
        for (int hh = 0; hh < 8; hh++) {
            const int h = part * 8 + hh;
            float v = __ldg(b1 + h);
#pragma unroll
            for (int k = 0; k < IN_DIM; k++)
                v = fmaf(a[k], __ldg(W1 + k * HID + h), v);
            hval[hh] = fmaxf(v, 0.0f);
        }

        // outputs o = part*4 .. part*4+3; hidden fetched from owning lane via shfl
        float acc0 = __ldg(b2 + part * 4 + 0);
        float acc1 = __ldg(b2 + part * 4 + 1);
        float acc2 = __ldg(b2 + part * 4 + 2);
        float acc3 = __ldg(b2 + part * 4 + 3);
#pragma unroll
        for (int h = 0; h < HID; h++) {
            const float hv = __shfl_sync(0xffffffffu, hval[h & 7], h >> 3, 8);
            const float* w = W2 + h * OUTD + part * 4;
            acc0 = fmaf(hv, __ldg(w + 0), acc0);
            acc1 = fmaf(hv, __ldg(w + 1), acc1);
            acc2 = fmaf(hv, __ldg(w + 2), acc2);
            acc3 = fmaf(hv, __ldg(w + 3), acc3);
        }

        if (active)
            *reinterpret_cast<float4*>(g_t + (size_t)node * OUTD + part * 4) =
                make_float4(acc0, acc1, acc2, acc3);
    }

    // ---- Grid barrier (all GRIDB blocks resident; self-resetting) ----
    __syncthreads();
    if (tid == 0) {
        __threadfence();                       // release: g_t rows visible first
        atomicAdd(&g_done, 1);
        volatile int* dp = &g_done;
        while (*dp < GRIDB) __nanosleep(64);
        __threadfence();                       // acquire + L1 invalidate
        if (atomicAdd(&g_exit, 1) == GRIDB - 1) {
            atomicExch(&g_done, 0);            // all blocks provably past wait
            atomicExch(&g_exit, 0);
        }
    }
    __syncthreads();

    // ---- Phase B: pair-row store stream ----
    const int q  = tid & 7;    // quad index (q*4 .. q*4+3 of the 32 outs)
    const int jl = tid >> 3;   // j lane (0..31)

    const float4* __restrict__ gt4 = reinterpret_cast<const float4*>(g_t);
    float4* __restrict__ out4 = reinterpret_cast<float4*>(out);

    for (int row = blockIdx.x; row < N_TOT; row += GRIDB) {
        int b = 0;
#pragma unroll
        for (int g = 1; g < NB; g++) b += (row >= c_starts[g]) ? 1 : 0;

        const int gbase = c_starts[b];
        const int nb    = c_sizes[b];
        const int i     = row - gbase;
        const int orow0 = c_paircum[b] + i * nb;

        const float4 ti = gt4[(size_t)row * 8 + q];

        int j = jl;            // jl < 32 <= nb always -> at least one trip
        float4 tj = gt4[(size_t)(gbase + j) * 8 + q];

        for (;;) {
            const int jn = j + 32;
            const bool more = jn < nb;
            float4 tn;
            if (more) tn = gt4[(size_t)(gbase + jn) * 8 + q];
            float4 r;
            r.x = ti.x + tj.x; r.y = ti.y + tj.y;
            r.z = ti.z + tj.z; r.w = ti.w + tj.w;
            __stcs(&out4[(size_t)(orow0 + j) * 8 + q], r);
            if (!more) break;
            j = jn; tj = tn;
        }
    }
}

extern "C" void kernel_launch(void* const* d_in, const int* in_sizes, int n_in,
                              void* d_out, int out_size)
{
    const float* ape = (const float*)d_in[0];
    const float* W1  = (const float*)d_in[1];
    const float* b1  = (const float*)d_in[2];
    const float* W2  = (const float*)d_in[3];
    const float* b2  = (const float*)d_in[4];
    float* out = (float*)d_out;

    fused_kernel<<<GRIDB, 256>>>(ape, W1, b1, W2, b2, out);
}

// round 8
// speedup vs baseline: 1.4822x; 1.1028x over previous
#include <cuda_runtime.h>

// Problem constants (static in the reference: SIZES[g] = 256 + 16*g, B=16)
#define NB 16
#define IN_DIM 16
#define HID 64
#define OUTD 32
#define N_TOT 6016
#define N_PAIRS 2349056
#define ITILE 8            // i-rows per pair block (all sizes divisible by 8)

// t scratch: per-node MLP output [N_TOT, 32] = 770 KB
__device__ float g_t[N_TOT * OUTD];

// starts[g] = sum_{h<g} sizes[h]; starts[16] = 6016 (sentinel)
__constant__ int c_starts[NB + 1] = {
    0, 256, 528, 816, 1120, 1440, 1776, 2128,
    2496, 2880, 3280, 3696, 4128, 4576, 5040, 5520, 6016};
__constant__ int c_sizes[NB] = {
    256, 272, 288, 304, 320, 336, 352, 368,
    384, 400, 416, 432, 448, 464, 480, 496};
// pair_cum[g] = sum_{h<g} sizes[h]^2
__constant__ int c_paircum[NB] = {
    0, 65536, 139520, 222464, 314880, 417280, 530176, 654080,
    789504, 936960, 1096960, 1270016, 1456640, 1657344, 1872640, 2103040};

// ---------------------------------------------------------------------------
// Kernel 1: per-node MLP  t[n] = relu(ape[n] @ W1 + b1) @ W2 + b2
// (unchanged from the 54.9us best — it is not the binder)
// ---------------------------------------------------------------------------
__global__ __launch_bounds__(128) void mlp_kernel(
    const float* __restrict__ ape, const float* __restrict__ W1,
    const float* __restrict__ b1, const float* __restrict__ W2,
    const float* __restrict__ b2)
{
    __shared__ float sW1[IN_DIM * HID];
    __shared__ float sW2[HID * OUTD];
    __shared__ float sb1[HID];
    __shared__ float sb2[OUTD];

    const int tid = threadIdx.x;
    for (int i = tid; i < IN_DIM * HID; i += blockDim.x) sW1[i] = W1[i];
    for (int i = tid; i < HID * OUTD; i += blockDim.x) sW2[i] = W2[i];
    if (tid < HID)  sb1[tid] = b1[tid];
    if (tid < OUTD) sb2[tid] = b2[tid];
    __syncthreads();

    const int n = blockIdx.x * blockDim.x + tid;
    if (n >= N_TOT) return;

    float a[IN_DIM];
    const float4* ap = reinterpret_cast<const float4*>(ape + (size_t)n * IN_DIM);
#pragma unroll
    for (int k4 = 0; k4 < IN_DIM / 4; k4++) {
        float4 v = __ldg(ap + k4);
        a[k4 * 4 + 0] = v.x; a[k4 * 4 + 1] = v.y;
        a[k4 * 4 + 2] = v.z; a[k4 * 4 + 3] = v.w;
    }

    float acc[OUTD];
#pragma unroll
    for (int o = 0; o < OUTD; o++) acc[o] = sb2[o];

#pragma unroll 4
    for (int h = 0; h < HID; h++) {
        float hh = sb1[h];
#pragma unroll
        for (int k = 0; k < IN_DIM; k++) hh = fmaf(a[k], sW1[k * HID + h], hh);
        hh = fmaxf(hh, 0.0f);
#pragma unroll
        for (int o = 0; o < OUTD; o++) acc[o] = fmaf(hh, sW2[h * OUTD + o], acc[o]);
    }

    float4* tp = reinterpret_cast<float4*>(g_t + (size_t)n * OUTD);
#pragma unroll
    for (int o4 = 0; o4 < OUTD / 4; o4++)
        tp[o4] = make_float4(acc[o4 * 4 + 0], acc[o4 * 4 + 1],
                             acc[o4 * 4 + 2], acc[o4 * 4 + 3]);
}

// ---------------------------------------------------------------------------
// Kernel 2: pairwise outer-sum with ITILE=8 i-rows per block.
// Each t[j] load is reused for 8 output rows -> L2 load traffic /8.
// Grid: 752 blocks (= N_TOT/8, exact: all graph sizes divisible by 8).
// Threads: 256 = 32 j-lanes x 8 quads. Warp stores 512 B contiguous per i.
// ---------------------------------------------------------------------------
__global__ __launch_bounds__(256) void pair_kernel(float* __restrict__ out)
{
    const int bb = blockIdx.x;                 // chunk id: rows [bb*8, bb*8+8)

    // which graph owns this chunk (chunk prefix = starts >> 3)
    int b = 0;
#pragma unroll
    for (int g = 1; g < NB; g++) b += (bb >= (c_starts[g] >> 3)) ? 1 : 0;

    const int gbase = c_starts[b];
    const int nb    = c_sizes[b];
    const int i0    = bb * ITILE - gbase;      // first local i of this chunk
    // output row for (i0+i, j) = c_paircum[b] + (i0+i)*nb + j
    const int obase = c_paircum[b] + i0 * nb;

    const int q  = threadIdx.x & 7;    // quad index (q*4 .. q*4+3 of the 32 outs)
    const int jl = threadIdx.x >> 3;   // j lane (0..31)

    const float4* __restrict__ gt4 = reinterpret_cast<const float4*>(g_t);
    float4* __restrict__ out4 = reinterpret_cast<float4*>(out);

    // hold the 8 ti rows (this thread's quad) in registers
    float4 ti[ITILE];
#pragma unroll
    for (int i = 0; i < ITILE; i++)
        ti[i] = __ldg(&gt4[(size_t)(gbase + i0 + i) * 8 + q]);

    int j = jl;                        // jl < 32 <= nb always -> at least one trip
    float4 tj = __ldg(&gt4[(size_t)(gbase + j) * 8 + q]);

    for (;;) {
        const int jn = j + 32;
        const bool more = jn < nb;
        float4 tn;
        if (more) tn = __ldg(&gt4[(size_t)(gbase + jn) * 8 + q]);

        const size_t o0 = (size_t)(obase + j) * 8 + q;   // float4 index of (i0, j, q)
#pragma unroll
        for (int i = 0; i < ITILE; i++) {
            float4 r;
            r.x = ti[i].x + tj.x; r.y = ti[i].y + tj.y;
            r.z = ti[i].z + tj.z; r.w = ti[i].w + tj.w;
            __stcs(&out4[o0 + (size_t)i * nb * 8], r);
        }
        if (!more) break;
        j = jn; tj = tn;
    }
}

extern "C" void kernel_launch(void* const* d_in, const int* in_sizes, int n_in,
                              void* d_out, int out_size)
{
    const float* ape = (const float*)d_in[0];
    const float* W1  = (const float*)d_in[1];
    const float* b1  = (const float*)d_in[2];
    const float* W2  = (const float*)d_in[3];
    const float* b2  = (const float*)d_in[4];
    float* out = (float*)d_out;

    mlp_kernel<<<(N_TOT + 127) / 128, 128>>>(ape, W1, b1, W2, b2);
    pair_kernel<<<N_TOT / ITILE, 256>>>(out);
}

// round 9
// speedup vs baseline: 1.5800x; 1.0660x over previous
#include <cuda_runtime.h>

// Problem constants (static in the reference: SIZES[g] = 256 + 16*g, B=16)
#define NB 16
#define IN_DIM 16
#define HID 64
#define OUTD 32
#define N_TOT 6016
#define N_PAIRS 2349056
#define ITILE 4            // i-rows per pair block (all sizes divisible by 4)

// t scratch: per-node MLP output [N_TOT, 32] = 770 KB
__device__ float g_t[N_TOT * OUTD];

// starts[g] = sum_{h<g} sizes[h]; starts[16] = 6016 (sentinel)
__constant__ int c_starts[NB + 1] = {
    0, 256, 528, 816, 1120, 1440, 1776, 2128,
    2496, 2880, 3280, 3696, 4128, 4576, 5040, 5520, 6016};
__constant__ int c_sizes[NB] = {
    256, 272, 288, 304, 320, 336, 352, 368,
    384, 400, 416, 432, 448, 464, 480, 496};
// pair_cum[g] = sum_{h<g} sizes[h]^2
__constant__ int c_paircum[NB] = {
    0, 65536, 139520, 222464, 314880, 417280, 530176, 654080,
    789504, 936960, 1096960, 1270016, 1456640, 1657344, 1872640, 2103040};

// ---------------------------------------------------------------------------
// Kernel 1: per-node MLP  t[n] = relu(ape[n] @ W1 + b1) @ W2 + b2
// (R3-proven version) + PDL trigger so the pair kernel launch overlaps.
// ---------------------------------------------------------------------------
__global__ __launch_bounds__(128) void mlp_kernel(
    const float* __restrict__ ape, const float* __restrict__ W1,
    const float* __restrict__ b1, const float* __restrict__ W2,
    const float* __restrict__ b2)
{
    __shared__ float sW1[IN_DIM * HID];
    __shared__ float sW2[HID * OUTD];
    __shared__ float sb1[HID];
    __shared__ float sb2[OUTD];

    const int tid = threadIdx.x;
    for (int i = tid; i < IN_DIM * HID; i += blockDim.x) sW1[i] = W1[i];
    for (int i = tid; i < HID * OUTD; i += blockDim.x) sW2[i] = W2[i];
    if (tid < HID)  sb1[tid] = b1[tid];
    if (tid < OUTD) sb2[tid] = b2[tid];
    __syncthreads();

    const int n = blockIdx.x * blockDim.x + tid;
    if (n < N_TOT) {
        float a[IN_DIM];
        const float4* ap = reinterpret_cast<const float4*>(ape + (size_t)n * IN_DIM);
#pragma unroll
        for (int k4 = 0; k4 < IN_DIM / 4; k4++) {
            float4 v = __ldg(ap + k4);
            a[k4 * 4 + 0] = v.x; a[k4 * 4 + 1] = v.y;
            a[k4 * 4 + 2] = v.z; a[k4 * 4 + 3] = v.w;
        }

        float acc[OUTD];
#pragma unroll
        for (int o = 0; o < OUTD; o++) acc[o] = sb2[o];

#pragma unroll 4
        for (int h = 0; h < HID; h++) {
            float hh = sb1[h];
#pragma unroll
            for (int k = 0; k < IN_DIM; k++) hh = fmaf(a[k], sW1[k * HID + h], hh);
            hh = fmaxf(hh, 0.0f);
#pragma unroll
            for (int o = 0; o < OUTD; o++) acc[o] = fmaf(hh, sW2[h * OUTD + o], acc[o]);
        }

        float4* tp = reinterpret_cast<float4*>(g_t + (size_t)n * OUTD);
#pragma unroll
        for (int o4 = 0; o4 < OUTD / 4; o4++)
            tp[o4] = make_float4(acc[o4 * 4 + 0], acc[o4 * 4 + 1],
                                 acc[o4 * 4 + 2], acc[o4 * 4 + 3]);
    }

    // PDL: allow the dependent pair kernel to begin launching now
    cudaTriggerProgrammaticLaunchCompletion();
}

// ---------------------------------------------------------------------------
// Kernel 2: pairwise outer-sum with ITILE=4 i-rows per block.
// Each t[j] load amortized over 4 output rows -> LTS load traffic /4
// (375 MB total vs 600 MB untiled) while keeping grid=1504 and >=5 CTAs/SM.
// Threads: 256 = 32 j-lanes x 8 quads; warp stores 512 B contiguous per row.
// PDL: index prologue runs before cudaGridDependencySynchronize().
// ---------------------------------------------------------------------------
__global__ __launch_bounds__(256, 5) void pair_kernel(float* __restrict__ out)
{
    // reversed chunk order: largest graphs (largest nb) scheduled first
    const int bb = (int)gridDim.x - 1 - (int)blockIdx.x;

    // which graph owns this chunk (chunk prefix = starts / ITILE)
    int b = 0;
#pragma unroll
    for (int g = 1; g < NB; g++) b += (bb >= (c_starts[g] / ITILE)) ? 1 : 0;

    const int gbase = c_starts[b];
    const int nb    = c_sizes[b];
    const int i0    = bb * ITILE - gbase;      // first local i of this chunk
    const int obase = c_paircum[b] + i0 * nb;  // output row of (i0, j=0)

    const int q  = threadIdx.x & 7;    // quad index (q*4 .. q*4+3 of the 32 outs)
    const int jl = threadIdx.x >> 3;   // j lane (0..31)

    const float4* __restrict__ gt4 = reinterpret_cast<const float4*>(g_t);
    float4* __restrict__ out4 = reinterpret_cast<float4*>(out);

    // wait for the MLP kernel's results before touching g_t
    cudaGridDependencySynchronize();

    // hold the ITILE ti rows (this thread's quad) in registers
    float4 ti[ITILE];
#pragma unroll
    for (int i = 0; i < ITILE; i++)
        ti[i] = __ldg(&gt4[(size_t)(gbase + i0 + i) * 8 + q]);

    int j = jl;                        // jl < 32 <= nb always -> at least one trip
    float4 tj = __ldg(&gt4[(size_t)(gbase + j) * 8 + q]);

    for (;;) {
        const int jn = j + 32;
        const bool more = jn < nb;
        float4 tn;
        if (more) tn = __ldg(&gt4[(size_t)(gbase + jn) * 8 + q]);

        const size_t o0 = (size_t)(obase + j) * 8 + q;   // float4 index of (i0, j, q)
#pragma unroll
        for (int i = 0; i < ITILE; i++) {
            float4 r;
            r.x = ti[i].x + tj.x; r.y = ti[i].y + tj.y;
            r.z = ti[i].z + tj.z; r.w = ti[i].w + tj.w;
            __stcs(&out4[o0 + (size_t)i * nb * 8], r);
        }
        if (!more) break;
        j = jn; tj = tn;
    }
}

extern "C" void kernel_launch(void* const* d_in, const int* in_sizes, int n_in,
                              void* d_out, int out_size)
{
    const float* ape = (const float*)d_in[0];
    const float* W1  = (const float*)d_in[1];
    const float* b1  = (const float*)d_in[2];
    const float* W2  = (const float*)d_in[3];
    const float* b2  = (const float*)d_in[4];
    float* out = (float*)d_out;

    mlp_kernel<<<(N_TOT + 127) / 128, 128>>>(ape, W1, b1, W2, b2);

    // PDL launch: pair kernel may begin (prologue) while mlp drains
    cudaLaunchAttribute attrs[1];
    attrs[0].id = cudaLaunchAttributeProgrammaticStreamSerialization;
    attrs[0].val.programmaticStreamSerializationAllowed = 1;
    cudaLaunchConfig_t cfg = {};
    cfg.gridDim  = dim3(N_TOT / ITILE, 1, 1);
    cfg.blockDim = dim3(256, 1, 1);
    cfg.dynamicSmemBytes = 0;
    cfg.stream = 0;
    cfg.attrs = attrs;
    cfg.numAttrs = 1;
    cudaLaunchKernelEx(&cfg, pair_kernel, out);
}

// round 10
// speedup vs baseline: 1.6590x; 1.0500x over previous
#include <cuda_runtime.h>

// Problem constants (static in the reference: SIZES[g] = 256 + 16*g, B=16)
#define NB 16
#define IN_DIM 16
#define HID 64
#define OUTD 32
#define N_TOT 6016
#define N_PAIRS 2349056
#define ITILE 2            // i-rows per pair block (all sizes divisible by 2)

// t scratch: per-node MLP output [N_TOT, 32] = 770 KB
__device__ float g_t[N_TOT * OUTD];

// starts[g] = sum_{h<g} sizes[h]; starts[16] = 6016 (sentinel)
__constant__ int c_starts[NB + 1] = {
    0, 256, 528, 816, 1120, 1440, 1776, 2128,
    2496, 2880, 3280, 3696, 4128, 4576, 5040, 5520, 6016};
__constant__ int c_sizes[NB] = {
    256, 272, 288, 304, 320, 336, 352, 368,
    384, 400, 416, 432, 448, 464, 480, 496};
// pair_cum[g] = sum_{h<g} sizes[h]^2
__constant__ int c_paircum[NB] = {
    0, 65536, 139520, 222464, 314880, 417280, 530176, 654080,
    789504, 936960, 1096960, 1270016, 1456640, 1657344, 1872640, 2103040};

// ---------------------------------------------------------------------------
// Kernel 1: per-node MLP  t[n] = relu(ape[n] @ W1 + b1) @ W2 + b2
// (R3-proven version) + PDL trigger so the pair kernel launch overlaps.
// ---------------------------------------------------------------------------
__global__ __launch_bounds__(128) void mlp_kernel(
    const float* __restrict__ ape, const float* __restrict__ W1,
    const float* __restrict__ b1, const float* __restrict__ W2,
    const float* __restrict__ b2)
{
    __shared__ float sW1[IN_DIM * HID];
    __shared__ float sW2[HID * OUTD];
    __shared__ float sb1[HID];
    __shared__ float sb2[OUTD];

    const int tid = threadIdx.x;
    for (int i = tid; i < IN_DIM * HID; i += blockDim.x) sW1[i] = W1[i];
    for (int i = tid; i < HID * OUTD; i += blockDim.x) sW2[i] = W2[i];
    if (tid < HID)  sb1[tid] = b1[tid];
    if (tid < OUTD) sb2[tid] = b2[tid];
    __syncthreads();

    const int n = blockIdx.x * blockDim.x + tid;
    if (n < N_TOT) {
        float a[IN_DIM];
        const float4* ap = reinterpret_cast<const float4*>(ape + (size_t)n * IN_DIM);
#pragma unroll
        for (int k4 = 0; k4 < IN_DIM / 4; k4++) {
            float4 v = __ldg(ap + k4);
            a[k4 * 4 + 0] = v.x; a[k4 * 4 + 1] = v.y;
            a[k4 * 4 + 2] = v.z; a[k4 * 4 + 3] = v.w;
        }

        float acc[OUTD];
#pragma unroll
        for (int o = 0; o < OUTD; o++) acc[o] = sb2[o];

#pragma unroll 4
        for (int h = 0; h < HID; h++) {
            float hh = sb1[h];
#pragma unroll
            for (int k = 0; k < IN_DIM; k++) hh = fmaf(a[k], sW1[k * HID + h], hh);
            hh = fmaxf(hh, 0.0f);
#pragma unroll
            for (int o = 0; o < OUTD; o++) acc[o] = fmaf(hh, sW2[h * OUTD + o], acc[o]);
        }

        float4* tp = reinterpret_cast<float4*>(g_t + (size_t)n * OUTD);
#pragma unroll
        for (int o4 = 0; o4 < OUTD / 4; o4++)
            tp[o4] = make_float4(acc[o4 * 4 + 0], acc[o4 * 4 + 1],
                                 acc[o4 * 4 + 2], acc[o4 * 4 + 3]);
    }

    // PDL: allow the dependent pair kernel to begin launching now
    cudaTriggerProgrammaticLaunchCompletion();
}

// ---------------------------------------------------------------------------
// Kernel 2: pairwise outer-sum with ITILE=2 i-rows per block.
// LTS traffic = 300 (stores) + 150 (loads) = 450 MB: below the ~6300 B/cyc
// chip LTS cap that bound the untiled version, while regs stay ~40 so 6
// CTAs/SM keep memory-level parallelism (the ITILE=4 failure mode).
// Threads: 256 = 32 j-lanes x 8 quads; warp stores 512 B contiguous per row.
// ---------------------------------------------------------------------------
__global__ __launch_bounds__(256, 6) void pair_kernel(float* __restrict__ out)
{
    // reversed chunk order: largest graphs (largest nb) scheduled first
    const int bb = (int)gridDim.x - 1 - (int)blockIdx.x;

    // which graph owns this chunk (chunk prefix = starts / ITILE)
    int b = 0;
#pragma unroll
    for (int g = 1; g < NB; g++) b += (bb >= (c_starts[g] / ITILE)) ? 1 : 0;

    const int gbase = c_starts[b];
    const int nb    = c_sizes[b];
    const int i0    = bb * ITILE - gbase;      // first local i of this chunk
    const int obase = c_paircum[b] + i0 * nb;  // output row of (i0, j=0)

    const int q  = threadIdx.x & 7;    // quad index (q*4 .. q*4+3 of the 32 outs)
    const int jl = threadIdx.x >> 3;   // j lane (0..31)

    const float4* __restrict__ gt4 = reinterpret_cast<const float4*>(g_t);
    float4* __restrict__ out4 = reinterpret_cast<float4*>(out);

    // wait for the MLP kernel's results before touching g_t
    cudaGridDependencySynchronize();

    // hold the ITILE ti rows (this thread's quad) in registers
    float4 ti0 = __ldg(&gt4[(size_t)(gbase + i0 + 0) * 8 + q]);
    float4 ti1 = __ldg(&gt4[(size_t)(gbase + i0 + 1) * 8 + q]);

    int j = jl;                        // jl < 32 <= nb always -> at least one trip
    float4 tj = __ldg(&gt4[(size_t)(gbase + j) * 8 + q]);

    for (;;) {
        const int jn = j + 32;
        const bool more = jn < nb;
        float4 tn;
        if (more) tn = __ldg(&gt4[(size_t)(gbase + jn) * 8 + q]);

        const size_t o0 = (size_t)(obase + j) * 8 + q;   // float4 index of (i0, j, q)
        float4 r0, r1;
        r0.x = ti0.x + tj.x; r0.y = ti0.y + tj.y;
        r0.z = ti0.z + tj.z; r0.w = ti0.w + tj.w;
        r1.x = ti1.x + tj.x; r1.y = ti1.y + tj.y;
        r1.z = ti1.z + tj.z; r1.w = ti1.w + tj.w;
        __stcs(&out4[o0], r0);
        __stcs(&out4[o0 + (size_t)nb * 8], r1);
        if (!more) break;
        j = jn; tj = tn;
    }
}

extern "C" void kernel_launch(void* const* d_in, const int* in_sizes, int n_in,
                              void* d_out, int out_size)
{
    const float* ape = (const float*)d_in[0];
    const float* W1  = (const float*)d_in[1];
    const float* b1  = (const float*)d_in[2];
    const float* W2  = (const float*)d_in[3];
    const float* b2  = (const float*)d_in[4];
    float* out = (float*)d_out;

    mlp_kernel<<<(N_TOT + 127) / 128, 128>>>(ape, W1, b1, W2, b2);

    // PDL launch: pair kernel may begin (prologue) while mlp drains
    cudaLaunchAttribute attrs[1];
    attrs[0].id = cudaLaunchAttributeProgrammaticStreamSerialization;
    attrs[0].val.programmaticStreamSerializationAllowed = 1;
    cudaLaunchConfig_t cfg = {};
    cfg.gridDim  = dim3(N_TOT / ITILE, 1, 1);
    cfg.blockDim = dim3(256, 1, 1);
    cfg.dynamicSmemBytes = 0;
    cfg.stream = 0;
    cfg.attrs = attrs;
    cfg.numAttrs = 1;
    cudaLaunchKernelEx(&cfg, pair_kernel, out);
}